// round 10
// baseline (speedup 1.0000x reference)
#include <cuda_runtime.h>
#include <cuda_fp16.h>
#include <math.h>
#include <stdint.h>

#define BB 16
#define C1 128
#define C2 256
#define KK 4
#define HH 80
#define WW 80
#define HW 6400
#define EPSF 1e-5f
#define NPX1 50    // px tiles (128 px each) for conv1 partial sums

// ---------------- helpers ----------------
__device__ __forceinline__ uint32_t packh2(float a, float b) {
    __half2 h = __floats2half2_rn(a, b);
    return *reinterpret_cast<uint32_t*>(&h);
}
__device__ __forceinline__ uint32_t smem_u32(const void* p) {
    uint32_t a;
    asm("{ .reg .u64 t; cvta.to.shared.u64 t, %1; cvt.u32.u64 %0, t; }"
        : "=r"(a) : "l"(p));
    return a;
}
__device__ __forceinline__ void ldsm_x4(uint32_t addr, uint32_t& r0, uint32_t& r1,
                                        uint32_t& r2, uint32_t& r3) {
    asm volatile("ldmatrix.sync.aligned.m8n8.x4.shared.b16 {%0,%1,%2,%3}, [%4];"
                 : "=r"(r0), "=r"(r1), "=r"(r2), "=r"(r3) : "r"(addr));
}
__device__ __forceinline__ void ldsm_x4_t(uint32_t addr, uint32_t& r0, uint32_t& r1,
                                          uint32_t& r2, uint32_t& r3) {
    asm volatile("ldmatrix.sync.aligned.m8n8.x4.trans.shared.b16 {%0,%1,%2,%3}, [%4];"
                 : "=r"(r0), "=r"(r1), "=r"(r2), "=r"(r3) : "r"(addr));
}
__device__ __forceinline__ void cp_async16(uint32_t dst, const void* src, uint32_t sz) {
    asm volatile("cp.async.cg.shared.global [%0], [%1], 16, %2;"
                 :: "r"(dst), "l"(src), "r"(sz) : "memory");
}
#define CP_COMMIT() asm volatile("cp.async.commit_group;" ::: "memory")
#define CP_WAIT0()  asm volatile("cp.async.wait_group 0;" ::: "memory")
#define MMA16816(acc, a, b)                                                    \
    asm volatile(                                                              \
        "mma.sync.aligned.m16n8k16.row.col.f32.f16.f16.f32 "                   \
        "{%0,%1,%2,%3}, {%4,%5,%6,%7}, {%8,%9}, {%0,%1,%2,%3};"                \
        : "+f"(acc[0]), "+f"(acc[1]), "+f"(acc[2]), "+f"(acc[3])               \
        : "r"(a[0]), "r"(a[1]), "r"(a[2]), "r"(a[3]), "r"(b[0]), "r"(b[1]))

// ---------------- scratch ----------------
__device__ float g_y[BB * C2 * HW];
__device__ float g_partsum[BB * C2 * NPX1];
__device__ float g_partsq [BB * C2 * NPX1];
__device__ float g_mu [BB * C2];
__device__ float g_inv[BB * C2];
__device__ float g_attn[BB * KK];
__device__ __half g_w1h[C2 * C1];                      // [oc][ic]
__device__ __half g_aggw16[(size_t)BB * 9 * C2 * C2];  // [b][tap][oc][ic]
__device__ float g_aggb[BB * C2];
__device__ uint32_t g_yh[(size_t)BB * HW * 128];       // [b][px][icpair] half2

// ============================================================================
// Kernel 0: convert w1 to fp16
// ============================================================================
__global__ void k_w1cvt(const float* __restrict__ w1)
{
    int i = blockIdx.x * 256 + threadIdx.x;
    if (i < C2 * C1) g_w1h[i] = __float2half_rn(w1[i]);
}

// ============================================================================
// Kernel A: conv1 as fp16 implicit GEMM (mma m16n8k16, fp32 accum).
// ============================================================================
#define A1_PITCH 80
#define A1_SZ    (128 * A1_PITCH)
#define B1_PITCH 272
#define B1_SZ    (32 * B1_PITCH)

__global__ void __launch_bounds__(256, 2) k_conv1(
    const float* __restrict__ x,
    const float* __restrict__ bng, const float* __restrict__ bnb,
    const float* __restrict__ bnm, const float* __restrict__ bnv)
{
    __shared__ __align__(16) uint8_t sA[2][A1_SZ];
    __shared__ __align__(16) uint8_t sB[2][B1_SZ];
    __shared__ float redS[2][128], redQ[2][128];

    const int tid = threadIdx.x;
    const int b   = blockIdx.z;
    const int oc0 = blockIdx.y * 128;
    const int p0  = blockIdx.x * 128;

    const int warp = tid >> 5;
    const int lane = tid & 31;
    const int wm   = warp >> 1;
    const int wn   = warp & 1;
    const int lr   = lane >> 2;
    const int lc   = lane & 3;

    const uint32_t sAu = smem_u32(sA);
    const uint32_t sBu = smem_u32(sB);
    const uint32_t lbase = (lane & 15);
    const uint32_t lcol  = (lane >> 4) * 16;
    const uint32_t aAddr0 = sAu + (wm * 32 + lbase) * A1_PITCH + lcol;
    const uint32_t bAddr0 = sBu + lbase * B1_PITCH + lcol + (wn * 64) * 2;

    const int a_row = tid >> 1;
    const int a_j0  = (tid & 1) * 2;
    const int b_kr  = warp * 4;

    const uint4* w1u = (const uint4*)g_w1h;
    const float* xb  = x + (size_t)b * C1 * HW + p0;

    float acc[2][8][4];
#pragma unroll
    for (int mt = 0; mt < 2; mt++)
#pragma unroll
        for (int nt = 0; nt < 8; nt++)
#pragma unroll
            for (int q = 0; q < 4; q++) acc[mt][nt][q] = 0.f;

    uint4 aR[2];
    uint32_t bR[4][2];

    auto load_st = [&](int s, int buf) {
#pragma unroll
        for (int i = 0; i < 2; i++)
            aR[i] = w1u[(oc0 + a_row) * 16 + s * 4 + a_j0 + i];
#pragma unroll
        for (int i = 0; i < 2; i++)
            *(uint4*)(sA[buf] + a_row * A1_PITCH + (a_j0 + i) * 16) = aR[i];
#pragma unroll
        for (int i = 0; i < 4; i++) {
            const int kr = b_kr + i;
            float4 v = *(const float4*)(xb + (size_t)(s * 32 + kr) * HW + lane * 4);
            bR[i][0] = packh2(v.x, v.y);
            bR[i][1] = packh2(v.z, v.w);
        }
#pragma unroll
        for (int i = 0; i < 4; i++)
            *(uint2*)(sB[buf] + (b_kr + i) * B1_PITCH + lane * 8) =
                make_uint2(bR[i][0], bR[i][1]);
    };

    load_st(0, 0);

    for (int s = 0; s < 4; s++) {
        __syncthreads();
        if (s < 3) load_st(s + 1, (s + 1) & 1);
        const int buf = s & 1;
#pragma unroll
        for (int ks = 0; ks < 2; ks++) {
            uint32_t afr[2][4];
#pragma unroll
            for (int mt = 0; mt < 2; mt++)
                ldsm_x4(aAddr0 + buf * A1_SZ + mt * (16 * A1_PITCH) + ks * 32,
                        afr[mt][0], afr[mt][1], afr[mt][2], afr[mt][3]);
            uint32_t bfr[8][2];
#pragma unroll
            for (int ng = 0; ng < 4; ng++) {
                uint32_t t0, t1, t2, t3;
                ldsm_x4_t(bAddr0 + buf * B1_SZ + ks * (16 * B1_PITCH) + ng * 32,
                          t0, t1, t2, t3);
                bfr[2 * ng][0] = t0; bfr[2 * ng][1] = t1;
                bfr[2 * ng + 1][0] = t2; bfr[2 * ng + 1][1] = t3;
            }
#pragma unroll
            for (int mt = 0; mt < 2; mt++)
#pragma unroll
                for (int nt = 0; nt < 8; nt++)
                    MMA16816(acc[mt][nt], afr[mt], bfr[nt]);
        }
    }

    float s4[4] = {0.f, 0.f, 0.f, 0.f};
    float q4[4] = {0.f, 0.f, 0.f, 0.f};
#pragma unroll
    for (int mt = 0; mt < 2; mt++) {
#pragma unroll
        for (int h = 0; h < 2; h++) {
            const int u  = mt * 2 + h;
            const int oc = oc0 + wm * 32 + mt * 16 + h * 8 + lr;
            const float sc = bng[oc] * rsqrtf(bnv[oc] + EPSF);
            const float bi = bnb[oc] - bnm[oc] * sc;
            float* ybase = &g_y[(size_t)(b * C2 + oc) * HW + p0];
#pragma unroll
            for (int nt = 0; nt < 8; nt++) {
                const int px = wn * 64 + nt * 8 + 2 * lc;
                float t0 = acc[mt][nt][h * 2 + 0] * sc + bi;
                float t1 = acc[mt][nt][h * 2 + 1] * sc + bi;
                float y0 = t0 / (1.f + expf(-t0));
                float y1 = t1 / (1.f + expf(-t1));
                s4[u] += y0 + y1;
                q4[u] += y0 * y0 + y1 * y1;
                *(float2*)&ybase[px] = make_float2(y0, y1);
            }
        }
    }
#pragma unroll
    for (int u = 0; u < 4; u++) {
        s4[u] += __shfl_xor_sync(0xffffffffu, s4[u], 1);
        s4[u] += __shfl_xor_sync(0xffffffffu, s4[u], 2);
        q4[u] += __shfl_xor_sync(0xffffffffu, q4[u], 1);
        q4[u] += __shfl_xor_sync(0xffffffffu, q4[u], 2);
    }
    __syncthreads();
    if (lc == 0) {
#pragma unroll
        for (int u = 0; u < 4; u++) {
            const int ocl = wm * 32 + (u >> 1) * 16 + (u & 1) * 8 + lr;
            redS[wn][ocl] = s4[u];
            redQ[wn][ocl] = q4[u];
        }
    }
    __syncthreads();
    if (tid < 128) {
        const size_t o = (size_t)(b * C2 + oc0 + tid) * NPX1 + blockIdx.x;
        g_partsum[o] = redS[0][tid] + redS[1][tid];
        g_partsq [o] = redQ[0][tid] + redQ[1][tid];
    }
}

// ============================================================================
// Kernel B1: stats
// ============================================================================
__global__ void k_stats()
{
    int i = blockIdx.x * blockDim.x + threadIdx.x;
    if (i >= BB * C2) return;
    const float* ps = &g_partsum[(size_t)i * NPX1];
    const float* pq = &g_partsq [(size_t)i * NPX1];
    float s = 0.f, q = 0.f;
    for (int j = 0; j < NPX1; j++) { s += ps[j]; q += pq[j]; }
    float mu  = s * (1.f / HW);
    float var = q * (1.f / HW) - mu * mu;
    g_mu[i]  = mu;
    g_inv[i] = rsqrtf(var + EPSF);
}

// ============================================================================
// Kernel B2: attention
// ============================================================================
__global__ void k_attn(
    const float* __restrict__ fc1w, const float* __restrict__ fc1b,
    const float* __restrict__ fc2w, const float* __restrict__ fc2b)
{
    int b = threadIdx.x >> 5;
    int lane = threadIdx.x & 31;
    float p4[KK] = {0.f, 0.f, 0.f, 0.f};
    for (int c = lane; c < C2; c += 32) {
        float pv = g_mu[b * C2 + c];
#pragma unroll
        for (int k = 0; k < KK; k++) p4[k] += pv * fc1w[k * C2 + c];
    }
#pragma unroll
    for (int off = 16; off > 0; off >>= 1)
#pragma unroll
        for (int k = 0; k < KK; k++)
            p4[k] += __shfl_down_sync(0xffffffffu, p4[k], off);
    if (lane == 0) {
        float a[KK];
#pragma unroll
        for (int k = 0; k < KK; k++) a[k] = fmaxf(p4[k] + fc1b[k], 0.f);
        float l[KK];
        float mx = -1e30f;
#pragma unroll
        for (int j = 0; j < KK; j++) {
            float t = fc2b[j];
#pragma unroll
            for (int k = 0; k < KK; k++) t += a[k] * fc2w[j * KK + k];
            l[j] = t;
            mx = fmaxf(mx, t);
        }
        float e[KK], s = 0.f;
#pragma unroll
        for (int j = 0; j < KK; j++) { e[j] = expf(l[j] - mx); s += e[j]; }
        float inv = 1.f / s;
#pragma unroll
        for (int j = 0; j < KK; j++) g_attn[b * KK + j] = e[j] * inv;
    }
}

// ============================================================================
// Kernel B3: normalize + transpose y -> [b][px][ic] fp16
// ============================================================================
__global__ void __launch_bounds__(256) k_norm()
{
    __shared__ float sm[32][257];
    __shared__ float s_mu[C2], s_inv[C2];

    const int px0 = blockIdx.x * 32;
    const int b   = blockIdx.y;
    const int tid = threadIdx.x;
    const int wid = tid >> 5;
    const int lane = tid & 31;

    if (tid < C2) {
        s_mu[tid]  = g_mu[b * C2 + tid];
        s_inv[tid] = g_inv[b * C2 + tid];
    }
    for (int c = wid; c < C2; c += 8)
        sm[lane][c] = g_y[(size_t)(b * C2 + c) * HW + px0 + lane];
    __syncthreads();

    const int px  = tid & 31;
    const int icg = tid >> 5;
    uint32_t o[16];
#pragma unroll
    for (int j = 0; j < 16; j++) {
        int ic = icg * 32 + 2 * j;
        float a = (sm[px][ic]     - s_mu[ic])     * s_inv[ic];
        float c = (sm[px][ic + 1] - s_mu[ic + 1]) * s_inv[ic + 1];
        o[j] = packh2(a, c);
    }
    uint4* dst = (uint4*)&g_yh[((size_t)(b * HW + px0 + px)) * 128 + icg * 16];
    dst[0] = make_uint4(o[0], o[1], o[2], o[3]);
    dst[1] = make_uint4(o[4], o[5], o[6], o[7]);
    dst[2] = make_uint4(o[8], o[9], o[10], o[11]);
    dst[3] = make_uint4(o[12], o[13], o[14], o[15]);
}

// ============================================================================
// Kernel C: agg weights -> fp16 [b][tap][oc][ic]
// ============================================================================
__global__ void __launch_bounds__(256) k_agg(
    const float* __restrict__ dyw, const float* __restrict__ dyb)
{
    __shared__ float s_attn[BB * KK];
    if (threadIdx.x < BB * KK) s_attn[threadIdx.x] = g_attn[threadIdx.x];
    __syncthreads();

    const int oc = blockIdx.x;
    const int ic = threadIdx.x;

    float d[KK][9];
#pragma unroll
    for (int k = 0; k < KK; k++) {
        const float* p = &dyw[((size_t)(k * C2 + oc) * C2 + ic) * 9];
#pragma unroll
        for (int tap = 0; tap < 9; tap++) d[k][tap] = p[tap];
    }
    for (int b = 0; b < BB; b++) {
        float a0 = s_attn[b * KK + 0], a1 = s_attn[b * KK + 1];
        float a2 = s_attn[b * KK + 2], a3 = s_attn[b * KK + 3];
#pragma unroll
        for (int tap = 0; tap < 9; tap++) {
            float w = a0 * d[0][tap] + a1 * d[1][tap] + a2 * d[2][tap] + a3 * d[3][tap];
            g_aggw16[(((size_t)b * 9 + tap) * C2 + oc) * C2 + ic] = __float2half_rn(w);
        }
    }
    if (ic == 0) {
        for (int b = 0; b < BB; b++) {
            float v = 0.f;
#pragma unroll
            for (int k = 0; k < KK; k++)
                v += s_attn[b * KK + k] * dyb[k * C2 + oc];
            g_aggb[b * C2 + oc] = v;
        }
    }
}

// ============================================================================
// Kernel D: dyconv as fp16 implicit GEMM, ldmatrix fragments, cp.async fill.
// CTA 128 oc x 128 px, 256 thr = 8 warps. 72 stages (9 taps x 32 ic),
// double-buffered; per stage: wait_group 0 -> sync -> async-fill(s+1)+commit
// -> compute(s). OOB handled by cp.async src-size 0 (zfill).
// ============================================================================
#define D_PITCH 80
#define D_SZ    (128 * D_PITCH)       // 10240

__global__ void __launch_bounds__(256, 2) k_dyconv(
    const float* __restrict__ b1g, const float* __restrict__ b1b,
    const float* __restrict__ b1m, const float* __restrict__ b1v,
    float* __restrict__ out)
{
    __shared__ __align__(16) uint8_t sA[2][D_SZ];
    __shared__ __align__(16) uint8_t sB[2][D_SZ];

    const int tid = threadIdx.x;
    const int b   = blockIdx.z;
    const int oc0 = blockIdx.y * 128;
    const int tyx = blockIdx.x;          // 0..49
    const int gy0 = (tyx / 5) * 8;
    const int gx0 = (tyx % 5) * 16;

    const int warp = tid >> 5;
    const int lane = tid & 31;
    const int wm   = warp >> 1;
    const int wn   = warp & 1;
    const int lr   = lane >> 2;
    const int lc   = lane & 3;

    const uint32_t sAu = smem_u32(sA);
    const uint32_t sBu = smem_u32(sB);
    const uint32_t lrow = (lane & 15);
    const uint32_t lcol = (lane >> 4) * 16;
    const uint32_t aAddr0 = sAu + (wm * 32 + lrow) * D_PITCH + lcol;
    const uint32_t bAddr0 = sBu + (wn * 64 + lrow) * D_PITCH + lcol;

    const int f_r = tid >> 2;            // 0..63
    const int f_j = tid & 3;

    const uint4* aggB = (const uint4*)(g_aggw16 + (size_t)b * 9 * C2 * C2);
    const uint4* yh4  = (const uint4*)(g_yh + (size_t)b * HW * 128);

    float acc[2][8][4];
#pragma unroll
    for (int mt = 0; mt < 2; mt++)
#pragma unroll
        for (int nt = 0; nt < 8; nt++)
#pragma unroll
            for (int q = 0; q < 4; q++) acc[mt][nt][q] = 0.f;

    // async fill of stage s into buffer buf (4 x 16B per thread)
    auto fill_async = [&](int s, int buf) {
        const int tap = s >> 3;
        const int icq = s & 7;
        const int dy  = tap / 3 - 1;
        const int dx  = tap % 3 - 1;
#pragma unroll
        for (int i = 0; i < 2; i++) {
            const int row = i * 64 + f_r;
            cp_async16(sAu + buf * D_SZ + row * D_PITCH + f_j * 16,
                       &aggB[((size_t)tap * C2 + oc0 + row) * 32 + icq * 4 + f_j], 16u);
            const int gy = gy0 + (row >> 4) + dy;
            const int gx = gx0 + (row & 15) + dx;
            const bool ok = ((unsigned)gy < (unsigned)HH) & ((unsigned)gx < (unsigned)WW);
            const uint4* src = ok ? &yh4[(size_t)(gy * WW + gx) * 32 + icq * 4 + f_j]
                                  : yh4;
            cp_async16(sBu + buf * D_SZ + row * D_PITCH + f_j * 16,
                       src, ok ? 16u : 0u);
        }
    };

    fill_async(0, 0);
    CP_COMMIT();

    for (int s = 0; s < 72; s++) {
        CP_WAIT0();
        __syncthreads();
        if (s < 71) { fill_async(s + 1, (s + 1) & 1); CP_COMMIT(); }

        const int buf = s & 1;
#pragma unroll
        for (int ks = 0; ks < 2; ks++) {
            uint32_t afr[2][4];
#pragma unroll
            for (int mt = 0; mt < 2; mt++)
                ldsm_x4(aAddr0 + buf * D_SZ + mt * (16 * D_PITCH) + ks * 32,
                        afr[mt][0], afr[mt][1], afr[mt][2], afr[mt][3]);
            uint32_t bfr[8][2];
#pragma unroll
            for (int ng = 0; ng < 4; ng++) {
                uint32_t t0, t1, t2, t3;
                ldsm_x4(bAddr0 + buf * D_SZ + ng * (16 * D_PITCH) + ks * 32,
                        t0, t1, t2, t3);
                bfr[2 * ng][0] = t0; bfr[2 * ng][1] = t2;
                bfr[2 * ng + 1][0] = t1; bfr[2 * ng + 1][1] = t3;
            }
#pragma unroll
            for (int mt = 0; mt < 2; mt++)
#pragma unroll
                for (int nt = 0; nt < 8; nt++)
                    MMA16816(acc[mt][nt], afr[mt], bfr[nt]);
        }
    }

    // ---- epilogue: + agg_b, bn1 affine, store ----
#pragma unroll
    for (int mt = 0; mt < 2; mt++) {
#pragma unroll
        for (int h = 0; h < 2; h++) {
            const int oc = oc0 + wm * 32 + mt * 16 + lr + h * 8;
            const float sc = b1g[oc] * rsqrtf(b1v[oc] + EPSF);
            const float bi = b1b[oc] - b1m[oc] * sc;
            const float ab = g_aggb[b * C2 + oc];
            float* obase = &out[(size_t)(b * C2 + oc) * HW];
#pragma unroll
            for (int nt = 0; nt < 8; nt++) {
                const int n0 = wn * 64 + nt * 8 + 2 * lc;
                const int gy = gy0 + (n0 >> 4);
                const int gx = gx0 + (n0 & 15);
                float2 o;
                o.x = (acc[mt][nt][h * 2 + 0] + ab) * sc + bi;
                o.y = (acc[mt][nt][h * 2 + 1] + ab) * sc + bi;
                *(float2*)&obase[gy * WW + gx] = o;
            }
        }
    }
}

// ============================================================================
extern "C" void kernel_launch(void* const* d_in, const int* in_sizes, int n_in,
                              void* d_out, int out_size)
{
    (void)in_sizes; (void)n_in; (void)out_size;
    const float* x    = (const float*)d_in[0];
    const float* w1   = (const float*)d_in[1];
    const float* bng  = (const float*)d_in[2];
    const float* bnb  = (const float*)d_in[3];
    const float* bnm  = (const float*)d_in[4];
    const float* bnv  = (const float*)d_in[5];
    const float* fc1w = (const float*)d_in[6];
    const float* fc1b = (const float*)d_in[7];
    const float* fc2w = (const float*)d_in[8];
    const float* fc2b = (const float*)d_in[9];
    const float* dyw  = (const float*)d_in[10];
    const float* dyb  = (const float*)d_in[11];
    const float* b1g  = (const float*)d_in[12];
    const float* b1b  = (const float*)d_in[13];
    const float* b1m  = (const float*)d_in[14];
    const float* b1v  = (const float*)d_in[15];
    float* out = (float*)d_out;

    k_w1cvt<<<128, 256>>>(w1);
    k_conv1<<<dim3(NPX1, 2, BB), 256>>>(x, bng, bnb, bnm, bnv);
    k_stats<<<(BB * C2 + 255) / 256, 256>>>();
    k_attn<<<1, 512>>>(fc1w, fc1b, fc2w, fc2b);
    k_norm<<<dim3(200, BB), 256>>>();
    k_agg<<<256, 256>>>(dyw, dyb);
    k_dyconv<<<dim3(50, 2, BB), 256>>>(b1g, b1b, b1m, b1v, out);
}